// round 7
// baseline (speedup 1.0000x reference)
#include <cuda_runtime.h>
#include <cuda_bf16.h>
#include <math.h>
#include <stdint.h>

#define T_STEPS 4096
#define HS 512
#define INSZ 2048
#define MBK 100
#define NCTA 128
#define NTHR 512

// ---------------- device scratch (allocations are forbidden) ----------------
__device__ float g_pre_rha[T_STEPS * HS];
__device__ float g_pre_rhm[T_STEPS * HS];
__device__ float g_pre_ca [T_STEPS * HS];
__device__ float g_pre_cm [T_STEPS * HS];
__device__ float g_pre_wpa[T_STEPS * MBK];
__device__ float g_pre_wpm[T_STEPS * MBK];
__device__ float g_state[3 * HS];          // [ha(512) | hm(512) | h(512)]
__device__ float g_r[HS];
__device__ float g_arlog[MBK];
__device__ float g_awalog[MBK];
__device__ float g_awmlog[MBK];
__device__ float g_awlog[3];
__device__ unsigned int g_arrive[NCTA * 32];   // one flag per CTA, 128B stride
__device__ unsigned int g_release;

__device__ __forceinline__ float warpsum(float v) {
#pragma unroll
    for (int o = 16; o; o >>= 1) v += __shfl_xor_sync(0xFFFFFFFFu, v, o);
    return v;
}

__device__ __forceinline__ unsigned int ld_acq(const unsigned int* p) {
    unsigned int v;
    asm volatile("ld.global.acquire.gpu.u32 %0, [%1];" : "=r"(v) : "l"(p));
    return v;
}
__device__ __forceinline__ void st_rel(unsigned int* p, unsigned int v) {
    asm volatile("st.global.release.gpu.u32 [%0], %1;" :: "l"(p), "r"(v));
}

// ---------------- atomic-free grid barrier (monotonic epochs) ----------------
__device__ __forceinline__ void bar_arrive(int cta, unsigned int barc) {
    __syncthreads();
    if (threadIdx.x == 0 && cta != 0) st_rel(&g_arrive[cta * 32], barc);
}
__device__ __forceinline__ void bar_wait(int cta, unsigned int barc) {
    if (cta == 0) {
        if (threadIdx.x < 32) {
            int lane = threadIdx.x;
            unsigned int a, b, c, d;
            do {
                a = (lane == 0) ? barc : ld_acq(&g_arrive[(lane      ) * 32]);
                b = ld_acq(&g_arrive[(lane + 32) * 32]);
                c = ld_acq(&g_arrive[(lane + 64) * 32]);
                d = ld_acq(&g_arrive[(lane + 96) * 32]);
            } while (min(min(a, b), min(c, d)) < barc);
            __syncwarp();
            if (lane == 0) st_rel(&g_release, barc);
        }
    } else {
        if (threadIdx.x == 0) {
            while (ld_acq(&g_release) < barc) {}
        }
    }
    __syncthreads();
}

__global__ void reset_kernel() {
    int i = blockIdx.x * blockDim.x + threadIdx.x;
    if (i < NCTA * 32) g_arrive[i] = 0u;
    if (i == 0) g_release = 0u;
}

// =====================================================================
// Precompute GEMMs: C[4096,N] = X[4096,2048] @ W[rowOff : rowOff+2048, 0:N] + bias
// One launch, gridDim.z = 6 jobs. 128x128 tile, K-tile 8, 256 threads, 8x8/thread.
// =====================================================================
__global__ __launch_bounds__(256)
void gemm6_kernel(const float* __restrict__ Xa, const float* __restrict__ Xm,
                  const float* __restrict__ W_rha, const float* __restrict__ b_rha,
                  const float* __restrict__ W_rhm, const float* __restrict__ b_rhm,
                  const float* __restrict__ W_ca,  const float* __restrict__ b_ca,
                  const float* __restrict__ W_cm,  const float* __restrict__ b_cm,
                  const float* __restrict__ W_wpa, const float* __restrict__ b_wpa,
                  const float* __restrict__ W_wpm, const float* __restrict__ b_wpm)
{
    const float* A; const float* B; const float* bias; float* C; int N; int rowOff;
    switch (blockIdx.z) {
        case 0: A = Xa; B = W_rha; bias = b_rha; C = g_pre_rha; N = HS;  rowOff = 0;   break;
        case 1: A = Xm; B = W_rhm; bias = b_rhm; C = g_pre_rhm; N = HS;  rowOff = 0;   break;
        case 2: A = Xa; B = W_ca;  bias = b_ca;  C = g_pre_ca;  N = HS;  rowOff = HS;  break;
        case 3: A = Xm; B = W_cm;  bias = b_cm;  C = g_pre_cm;  N = HS;  rowOff = HS;  break;
        case 4: A = Xa; B = W_wpa; bias = b_wpa; C = g_pre_wpa; N = MBK; rowOff = HS;  break;
        default:A = Xm; B = W_wpm; bias = b_wpm; C = g_pre_wpm; N = MBK; rowOff = HS;  break;
    }
    if ((int)blockIdx.x * 128 >= N) return;

    const int K = INSZ;
    __shared__ float As[8][128];
    __shared__ float Bs[8][128];
    const int tid  = threadIdx.x;
    const int tx   = tid & 15, ty = tid >> 4;
    const int brow = blockIdx.y, bcol = blockIdx.x;

    const int arow = tid >> 1, akq = (tid & 1) * 4;
    const float* Ag = A + (size_t)(brow * 128 + arow) * K + akq;
    const int bk = tid >> 5, bc = (tid & 31) * 4;
    const int gcol = bcol * 128 + bc;
    const bool bok = (gcol + 3 < N);

    float acc[8][8];
#pragma unroll
    for (int i = 0; i < 8; i++)
#pragma unroll
        for (int j = 0; j < 8; j++) acc[i][j] = 0.f;

    for (int k0 = 0; k0 < K; k0 += 8) {
        float4 av = *(const float4*)(Ag + k0);
        As[akq + 0][arow] = av.x; As[akq + 1][arow] = av.y;
        As[akq + 2][arow] = av.z; As[akq + 3][arow] = av.w;
        float4 bv = bok ? *(const float4*)(B + (size_t)(rowOff + k0 + bk) * N + gcol)
                        : make_float4(0.f, 0.f, 0.f, 0.f);
        *(float4*)&Bs[bk][bc] = bv;
        __syncthreads();
#pragma unroll
        for (int kk = 0; kk < 8; ++kk) {
            float ra[8], rb[8];
            *(float4*)(ra)     = *(const float4*)&As[kk][ty * 4];
            *(float4*)(ra + 4) = *(const float4*)&As[kk][64 + ty * 4];
            *(float4*)(rb)     = *(const float4*)&Bs[kk][tx * 4];
            *(float4*)(rb + 4) = *(const float4*)&Bs[kk][64 + tx * 4];
#pragma unroll
            for (int i = 0; i < 8; i++)
#pragma unroll
                for (int j = 0; j < 8; j++) acc[i][j] = fmaf(ra[i], rb[j], acc[i][j]);
        }
        __syncthreads();
    }
#pragma unroll
    for (int i = 0; i < 8; i++) {
        int row = brow * 128 + ((i < 4) ? (ty * 4 + i) : (64 + ty * 4 + i - 4));
#pragma unroll
        for (int j = 0; j < 8; j++) {
            int col = bcol * 128 + ((j < 4) ? (tx * 4 + j) : (64 + tx * 4 + j - 4));
            if (col < N) C[(size_t)row * N + col] = acc[i][j] + bias[col];
        }
    }
}

// =====================================================================
// Persistent sequential kernel: 128 CTAs x 512 threads, each owns 4 HS columns.
// =====================================================================
struct SeqSmem {
    float wrh [4][1024];   // W_rh  col slices: rows [r(512) | h(512)]
    float wrha[4][1024];   // W_rha rows 2048..3071: [r | ha]
    float wrhm[4][1024];   // W_rhm rows 2048..3071: [r | hm]
    float wca [4][512];    // W_ca rows 0..511 (ha)
    float wcm [4][512];    // W_cm rows 0..511 (hm)
    float wrp [1536];      // ar column (cta<100) or aw column (cta 100..102)
    float wwpa[512];       // W_wpa rows 0..511 (ha part), cta<100
    float wwpm[512];
    float mem [4][MBK];    // mem[:, owned cols], col-major
    float sx  [1536];      // state: [ha | hm | h]
    float r   [512];
    float lar [MBK], lawa[MBK], lawm[MBK], law[3];
    float par [MBK], pawa[MBK], pawm[MBK], aw[3];
    float red [8];
    float pre_ca[4], pre_cm[4], pre_rha[4], pre_rhm[4];
    float ca_own[4], cm_own[4];
    float brh[4];
    float brp1, bwp1, pre_wpa1, pre_wpm1;
};

__global__ __launch_bounds__(NTHR, 1)
void seq_kernel(const float* __restrict__ W_ca,  const float* __restrict__ W_cm,
                const float* __restrict__ W_wp,  const float* __restrict__ b_wp,
                const float* __restrict__ W_wpa, const float* __restrict__ W_wpm,
                const float* __restrict__ W_rp,  const float* __restrict__ b_rp,
                const float* __restrict__ W_rh,  const float* __restrict__ b_rh,
                const float* __restrict__ W_rha, const float* __restrict__ W_rhm,
                float* __restrict__ out)
{
    extern __shared__ float smem_raw[];
    SeqSmem& s = *reinterpret_cast<SeqSmem*>(smem_raw);
    const int tid  = threadIdx.x;
    const int warp = tid >> 5, lane = tid & 31;
    const int cta  = blockIdx.x;
    const int c4   = cta * 4;

    // ---- one-time weight load (column slices, column-major in SMEM) ----
    for (int idx = tid; idx < 4 * 1024; idx += NTHR) {
        int col = idx & 3, i = idx >> 2;
        s.wrh [col][i] = __ldg(&W_rh [(size_t)i * HS + c4 + col]);
        s.wrha[col][i] = __ldg(&W_rha[(size_t)(INSZ + i) * HS + c4 + col]);
        s.wrhm[col][i] = __ldg(&W_rhm[(size_t)(INSZ + i) * HS + c4 + col]);
    }
    for (int idx = tid; idx < 4 * 512; idx += NTHR) {
        int col = idx & 3, i = idx >> 2;
        s.wca[col][i] = __ldg(&W_ca[(size_t)i * HS + c4 + col]);
        s.wcm[col][i] = __ldg(&W_cm[(size_t)i * HS + c4 + col]);
    }
    if (cta < MBK) {
        for (int i = tid; i < 1536; i += NTHR) s.wrp[i] = __ldg(&W_rp[(size_t)i * MBK + cta]);
        for (int i = tid; i < 512; i += NTHR) {
            s.wwpa[i] = __ldg(&W_wpa[(size_t)i * MBK + cta]);
            s.wwpm[i] = __ldg(&W_wpm[(size_t)i * MBK + cta]);
        }
        if (tid == 0) s.brp1 = b_rp[cta];
    } else if (cta < MBK + 3) {
        for (int i = tid; i < 1536; i += NTHR) s.wrp[i] = __ldg(&W_wp[(size_t)i * 3 + (cta - MBK)]);
        if (tid == 0) s.bwp1 = b_wp[cta - MBK];
    }
    if (tid < 4) s.brh[tid] = b_rh[c4 + tid];
    for (int idx = tid; idx < 4 * MBK; idx += NTHR) (&s.mem[0][0])[idx] = 0.f;
    __syncthreads();

    unsigned int barc = 0;

    for (int t = 0; t < T_STEPS; ++t) {
        // ================= phase 1: state load + content cols + logits =================
        if (t == 0) {
            for (int i = tid; i < 1536; i += NTHR) s.sx[i] = 0.f;
        } else {
            for (int i = tid; i < 1536; i += NTHR) s.sx[i] = __ldcg(&g_state[i]);
        }
        if (tid < 4) {
            s.pre_ca [tid] = g_pre_ca [(size_t)t * HS + c4 + tid];
            s.pre_cm [tid] = g_pre_cm [(size_t)t * HS + c4 + tid];
            s.pre_rha[tid] = g_pre_rha[(size_t)t * HS + c4 + tid];
            s.pre_rhm[tid] = g_pre_rhm[(size_t)t * HS + c4 + tid];
        }
        if (tid == 4 && cta < MBK) {
            s.pre_wpa1 = g_pre_wpa[(size_t)t * MBK + cta];
            s.pre_wpm1 = g_pre_wpm[(size_t)t * MBK + cta];
        }
        __syncthreads();

        // 16 warps concurrently: c_a cols (w0-3), c_m cols (w4-7),
        // wrp logit segments (w8-13), aw_a/aw_m logits (w14/15)
        if (warp < 8) {
            int col = warp & 3;
            const float* w = (warp < 4) ? s.wca[col] : s.wcm[col];
            const float* x = (warp < 4) ? s.sx : (s.sx + 512);
            float acc = 0.f;
#pragma unroll
            for (int i = 0; i < 512; i += 32) acc = fmaf(x[i + lane], w[i + lane], acc);
            acc = warpsum(acc);
            if (lane == 0) {
                if (warp < 4) s.ca_own[col] = fmaxf(acc + s.pre_ca[col], 0.f);
                else          s.cm_own[col] = fmaxf(acc + s.pre_cm[col], 0.f);
            }
        } else if (warp < 14) {
            if (cta < MBK + 3) {
                float acc = 0.f; int base = (warp - 8) * 256;
#pragma unroll
                for (int i = 0; i < 256; i += 32)
                    acc = fmaf(s.sx[base + i + lane], s.wrp[base + i + lane], acc);
                acc = warpsum(acc);
                if (lane == 0) s.red[warp - 8] = acc;
            }
        } else {
            if (cta < MBK) {
                const float* w = (warp == 14) ? s.wwpa : s.wwpm;
                const float* x = (warp == 14) ? s.sx : (s.sx + 512);
                float acc = 0.f;
#pragma unroll
                for (int i = 0; i < 512; i += 32) acc = fmaf(x[i + lane], w[i + lane], acc);
                acc = warpsum(acc);
                if (lane == 0) s.red[6 + (warp - 14)] = acc;
            }
        }
        __syncthreads();
        if (tid == 0 && cta < MBK + 3) {
            float v = s.red[0] + s.red[1] + s.red[2] + s.red[3] + s.red[4] + s.red[5];
            if (cta < MBK) __stcg(&g_arlog[cta], v + s.brp1);
            else           __stcg(&g_awlog[cta - MBK], v + s.bwp1);
        }
        if (tid == 32 && cta < MBK) {
            __stcg(&g_awalog[cta], s.red[6] + s.pre_wpa1);
            __stcg(&g_awmlog[cta], s.red[7] + s.pre_wpm1);
        }
        ++barc; bar_arrive(cta, barc); bar_wait(cta, barc);

        // ================= phase 2: softmaxes + r =================
        if (tid < MBK) {
            s.lar [tid] = __ldcg(&g_arlog [tid]);
            s.lawa[tid] = __ldcg(&g_awalog[tid]);
            s.lawm[tid] = __ldcg(&g_awmlog[tid]);
        } else if (tid < MBK + 3) {
            s.law[tid - MBK] = __ldcg(&g_awlog[tid - MBK]);
        }
        __syncthreads();

        if (warp < 3) {
            const float* L = (warp == 0) ? s.lar : (warp == 1) ? s.lawa : s.lawm;
            float* P       = (warp == 0) ? s.par : (warp == 1) ? s.pawa : s.pawm;
            float v[4];
#pragma unroll
            for (int k = 0; k < 4; k++) { int j = lane + 32 * k; v[k] = (j < MBK) ? L[j] : -1e30f; }
            float m = fmaxf(fmaxf(v[0], v[1]), fmaxf(v[2], v[3]));
#pragma unroll
            for (int o = 16; o; o >>= 1) m = fmaxf(m, __shfl_xor_sync(0xFFFFFFFFu, m, o));
            float e[4], sum = 0.f;
#pragma unroll
            for (int k = 0; k < 4; k++) {
                int j = lane + 32 * k;
                e[k] = (j < MBK) ? expf(v[k] - m) : 0.f;
                sum += e[k];
            }
            sum = warpsum(sum);
            float inv = 1.f / sum;
#pragma unroll
            for (int k = 0; k < 4; k++) { int j = lane + 32 * k; if (j < MBK) P[j] = e[k] * inv; }
        } else if (warp == 3 && lane == 0) {
            float l0 = s.law[0], l1 = s.law[1], l2 = s.law[2];
            float m = fmaxf(l0, fmaxf(l1, l2));
            float e0 = expf(l0 - m), e1 = expf(l1 - m), e2 = expf(l2 - m);
            float inv = 1.f / (e0 + e1 + e2);
            s.aw[0] = e0 * inv; s.aw[1] = e1 * inv; s.aw[2] = e2 * inv;
        }
        __syncthreads();

        // r[owned cols] from OLD mem
        if (warp < 4) {
            int col = warp; float acc = 0.f;
            for (int j = lane; j < MBK; j += 32) acc = fmaf(s.par[j], s.mem[col][j], acc);
            acc = warpsum(acc);
            if (lane == 0) __stcg(&g_r[c4 + col], acc);
        }
        ++barc; bar_arrive(cta, barc);

        // mem update (purely local) overlaps the barrier wait
        {
            float aw0 = s.aw[0], aw1 = s.aw[1], aw2 = s.aw[2];
            for (int idx = tid; idx < 4 * MBK; idx += NTHR) {
                int col = idx & 3, j = idx >> 2;
                s.mem[col][j] = aw0 * s.mem[col][j]
                              + aw1 * s.pawa[j] * s.ca_own[col]
                              + aw2 * s.pawm[j] * s.cm_own[col];
            }
        }
        bar_wait(cta, barc);

        // ================= phase 3: h1 / ha1 / hm1 (12 warp-dots, one round) =================
        for (int i = tid; i < 512; i += NTHR) s.r[i] = __ldcg(&g_r[i]);
        __syncthreads();
        if (warp < 12) {
            int mat = warp >> 2, col = warp & 3;
            const float* w = (mat == 0) ? s.wrh[col] : (mat == 1) ? s.wrha[col] : s.wrhm[col];
            const float* x = (mat == 0) ? (s.sx + 1024) : (mat == 1) ? s.sx : (s.sx + 512);
            float acc = 0.f;
#pragma unroll
            for (int i = lane; i < 512; i += 32)
                acc = fmaf(s.r[i], w[i], fmaf(x[i], w[512 + i], acc));
            acc = warpsum(acc);
            if (lane == 0) {
                if (mat == 0) {
                    float h1 = fmaxf(acc + s.brh[col], 0.f);
                    __stcg(&g_state[1024 + c4 + col], h1);
                    out[(size_t)t * HS + c4 + col] = h1;
                } else if (mat == 1) {
                    __stcg(&g_state[c4 + col], fmaxf(acc + s.pre_rha[col], 0.f));
                } else {
                    __stcg(&g_state[512 + c4 + col], fmaxf(acc + s.pre_rhm[col], 0.f));
                }
            }
        }
        ++barc; bar_arrive(cta, barc); bar_wait(cta, barc);
    }
}

// =====================================================================
extern "C" void kernel_launch(void* const* d_in, const int* in_sizes, int n_in,
                              void* d_out, int out_size)
{
    const float* Xa    = (const float*)d_in[0];
    const float* Xm    = (const float*)d_in[1];
    const float* W_ca  = (const float*)d_in[2];
    const float* b_ca  = (const float*)d_in[3];
    const float* W_cm  = (const float*)d_in[4];
    const float* b_cm  = (const float*)d_in[5];
    const float* W_wp  = (const float*)d_in[6];
    const float* b_wp  = (const float*)d_in[7];
    const float* W_wpa = (const float*)d_in[8];
    const float* b_wpa = (const float*)d_in[9];
    const float* W_wpm = (const float*)d_in[10];
    const float* b_wpm = (const float*)d_in[11];
    const float* W_rp  = (const float*)d_in[12];
    const float* b_rp  = (const float*)d_in[13];
    const float* W_rh  = (const float*)d_in[14];
    const float* b_rh  = (const float*)d_in[15];
    const float* W_rha = (const float*)d_in[16];
    const float* W_rhm = (const float*)d_in[18];
    float* out = (float*)d_out;

    static bool attr_set = false;
    if (!attr_set) {
        cudaFuncSetAttribute(seq_kernel, cudaFuncAttributeMaxDynamicSharedMemorySize,
                             (int)sizeof(SeqSmem));
        attr_set = true;
    }

    dim3 ggrid(4, T_STEPS / 128, 6);
    gemm6_kernel<<<ggrid, 256>>>(Xa, Xm,
                                 W_rha, (const float*)d_in[17],
                                 W_rhm, (const float*)d_in[19],
                                 W_ca, b_ca, W_cm, b_cm,
                                 W_wpa, b_wpa, W_wpm, b_wpm);
    reset_kernel<<<8, 512>>>();
    seq_kernel<<<NCTA, NTHR, sizeof(SeqSmem)>>>(W_ca, W_cm, W_wp, b_wp, W_wpa, W_wpm,
                                                W_rp, b_rp, W_rh, b_rh, W_rha, W_rhm,
                                                out);
}

// round 8
// speedup vs baseline: 1.3283x; 1.3283x over previous
#include <cuda_runtime.h>
#include <cuda_bf16.h>
#include <math.h>
#include <stdint.h>

#define T_STEPS 4096
#define HS 512
#define INSZ 2048
#define MBK 100
#define NCTA 128
#define NTHR 256
#define NGRP 16
#define GRPSZ 8

// ---------------- device scratch (allocations are forbidden) ----------------
__device__ float g_pre_rha[T_STEPS * HS];
__device__ float g_pre_rhm[T_STEPS * HS];
__device__ float g_pre_ca [T_STEPS * HS];
__device__ float g_pre_cm [T_STEPS * HS];
__device__ float g_pre_wpa[T_STEPS * MBK];
__device__ float g_pre_wpm[T_STEPS * MBK];
__device__ float g_state[3 * HS];          // [ha(512) | hm(512) | h(512)]
__device__ float g_r[HS];
__device__ float g_arlog[MBK];
__device__ float g_awalog[MBK];
__device__ float g_awmlog[MBK];
__device__ float g_awlog[3];
__device__ unsigned int g_gbar[NGRP * 32]; // group counters, 128B apart
__device__ unsigned int g_rbar;            // root counter

__device__ __forceinline__ float warpsum(float v) {
#pragma unroll
    for (int o = 16; o; o >>= 1) v += __shfl_xor_sync(0xFFFFFFFFu, v, o);
    return v;
}

// ---------------- two-level atomic grid barrier ----------------
// Level 1: 16 group counters (8 CTAs each) -> per-address concurrency 8.
// The arrival that completes its group (old == 8*barc - 1) forwards ONE add
// to the root counter (concurrency 16). Everyone spins on the root.
__device__ __forceinline__ void gbar_arrive(int cta, unsigned int barc) {
    __syncthreads();
    if (threadIdx.x == 0) {
        __threadfence();
        unsigned int old = atomicAdd(&g_gbar[(cta >> 3) * 32], 1u);
        if (old == barc * GRPSZ - 1u) atomicAdd(&g_rbar, 1u);
    }
}
__device__ __forceinline__ void gbar_wait(unsigned int barc) {
    if (threadIdx.x == 0) {
        while (*(volatile unsigned int*)&g_rbar < barc * NGRP) {}
        __threadfence();
    }
    __syncthreads();
}

__global__ void reset_kernel() {
    int i = blockIdx.x * blockDim.x + threadIdx.x;
    if (i < NGRP * 32) g_gbar[i] = 0u;
    if (i == 0) g_rbar = 0u;
}

// =====================================================================
// Precompute GEMMs: C[4096,N] = X[4096,2048] @ W[rowOff : rowOff+2048, 0:N] + bias
// One launch, gridDim.z = 6 jobs. 128x128 tile, K-tile 8, 256 threads, 8x8/thread.
// =====================================================================
__global__ __launch_bounds__(256)
void gemm6_kernel(const float* __restrict__ Xa, const float* __restrict__ Xm,
                  const float* __restrict__ W_rha, const float* __restrict__ b_rha,
                  const float* __restrict__ W_rhm, const float* __restrict__ b_rhm,
                  const float* __restrict__ W_ca,  const float* __restrict__ b_ca,
                  const float* __restrict__ W_cm,  const float* __restrict__ b_cm,
                  const float* __restrict__ W_wpa, const float* __restrict__ b_wpa,
                  const float* __restrict__ W_wpm, const float* __restrict__ b_wpm)
{
    const float* A; const float* B; const float* bias; float* C; int N; int rowOff;
    switch (blockIdx.z) {
        case 0: A = Xa; B = W_rha; bias = b_rha; C = g_pre_rha; N = HS;  rowOff = 0;   break;
        case 1: A = Xm; B = W_rhm; bias = b_rhm; C = g_pre_rhm; N = HS;  rowOff = 0;   break;
        case 2: A = Xa; B = W_ca;  bias = b_ca;  C = g_pre_ca;  N = HS;  rowOff = HS;  break;
        case 3: A = Xm; B = W_cm;  bias = b_cm;  C = g_pre_cm;  N = HS;  rowOff = HS;  break;
        case 4: A = Xa; B = W_wpa; bias = b_wpa; C = g_pre_wpa; N = MBK; rowOff = HS;  break;
        default:A = Xm; B = W_wpm; bias = b_wpm; C = g_pre_wpm; N = MBK; rowOff = HS;  break;
    }
    if ((int)blockIdx.x * 128 >= N) return;

    const int K = INSZ;
    __shared__ float As[8][128];
    __shared__ float Bs[8][128];
    const int tid  = threadIdx.x;
    const int tx   = tid & 15, ty = tid >> 4;
    const int brow = blockIdx.y, bcol = blockIdx.x;

    const int arow = tid >> 1, akq = (tid & 1) * 4;
    const float* Ag = A + (size_t)(brow * 128 + arow) * K + akq;
    const int bk = tid >> 5, bc = (tid & 31) * 4;
    const int gcol = bcol * 128 + bc;
    const bool bok = (gcol + 3 < N);

    float acc[8][8];
#pragma unroll
    for (int i = 0; i < 8; i++)
#pragma unroll
        for (int j = 0; j < 8; j++) acc[i][j] = 0.f;

    for (int k0 = 0; k0 < K; k0 += 8) {
        float4 av = *(const float4*)(Ag + k0);
        As[akq + 0][arow] = av.x; As[akq + 1][arow] = av.y;
        As[akq + 2][arow] = av.z; As[akq + 3][arow] = av.w;
        float4 bv = bok ? *(const float4*)(B + (size_t)(rowOff + k0 + bk) * N + gcol)
                        : make_float4(0.f, 0.f, 0.f, 0.f);
        *(float4*)&Bs[bk][bc] = bv;
        __syncthreads();
#pragma unroll
        for (int kk = 0; kk < 8; ++kk) {
            float ra[8], rb[8];
            *(float4*)(ra)     = *(const float4*)&As[kk][ty * 4];
            *(float4*)(ra + 4) = *(const float4*)&As[kk][64 + ty * 4];
            *(float4*)(rb)     = *(const float4*)&Bs[kk][tx * 4];
            *(float4*)(rb + 4) = *(const float4*)&Bs[kk][64 + tx * 4];
#pragma unroll
            for (int i = 0; i < 8; i++)
#pragma unroll
                for (int j = 0; j < 8; j++) acc[i][j] = fmaf(ra[i], rb[j], acc[i][j]);
        }
        __syncthreads();
    }
#pragma unroll
    for (int i = 0; i < 8; i++) {
        int row = brow * 128 + ((i < 4) ? (ty * 4 + i) : (64 + ty * 4 + i - 4));
#pragma unroll
        for (int j = 0; j < 8; j++) {
            int col = bcol * 128 + ((j < 4) ? (tx * 4 + j) : (64 + tx * 4 + j - 4));
            if (col < N) C[(size_t)row * N + col] = acc[i][j] + bias[col];
        }
    }
}

// =====================================================================
// Persistent sequential kernel: 128 CTAs x 256 threads, each owns 4 HS columns.
// =====================================================================
struct SeqSmem {
    float wrh [4][1024];   // W_rh  col slices: rows [r(512) | h(512)]
    float wrha[4][1024];   // W_rha rows 2048..3071: [r | ha]
    float wrhm[4][1024];   // W_rhm rows 2048..3071: [r | hm]
    float wca [4][512];    // W_ca rows 0..511 (ha)
    float wcm [4][512];    // W_cm rows 0..511 (hm)
    float wrp [1536];      // ar column (cta<100) or aw column (cta 100..102)
    float wwpa[512];       // W_wpa rows 0..511 (ha part), cta<100
    float wwpm[512];
    float mem [4][MBK];    // mem[:, owned cols], col-major
    float sx  [1536];      // state: [ha | hm | h]
    float r   [512];
    float lar [MBK], lawa[MBK], lawm[MBK], law[3];
    float par [MBK], pawa[MBK], pawm[MBK], aw[3];
    float red [8];
    float pre_ca[4], pre_cm[4], pre_rha[4], pre_rhm[4];
    float ca_own[4], cm_own[4];
    float brh[4];
    float brp1, bwp1, pre_wpa1, pre_wpm1;
};

__global__ __launch_bounds__(NTHR, 1)
void seq_kernel(const float* __restrict__ W_ca,  const float* __restrict__ W_cm,
                const float* __restrict__ W_wp,  const float* __restrict__ b_wp,
                const float* __restrict__ W_wpa, const float* __restrict__ W_wpm,
                const float* __restrict__ W_rp,  const float* __restrict__ b_rp,
                const float* __restrict__ W_rh,  const float* __restrict__ b_rh,
                const float* __restrict__ W_rha, const float* __restrict__ W_rhm,
                float* __restrict__ out)
{
    extern __shared__ float smem_raw[];
    SeqSmem& s = *reinterpret_cast<SeqSmem*>(smem_raw);
    const int tid  = threadIdx.x;
    const int warp = tid >> 5, lane = tid & 31;
    const int cta  = blockIdx.x;
    const int c4   = cta * 4;

    // ---- one-time weight load (column slices, column-major in SMEM) ----
    for (int idx = tid; idx < 4 * 1024; idx += NTHR) {
        int col = idx & 3, i = idx >> 2;
        s.wrh [col][i] = __ldg(&W_rh [(size_t)i * HS + c4 + col]);
        s.wrha[col][i] = __ldg(&W_rha[(size_t)(INSZ + i) * HS + c4 + col]);
        s.wrhm[col][i] = __ldg(&W_rhm[(size_t)(INSZ + i) * HS + c4 + col]);
    }
    for (int idx = tid; idx < 4 * 512; idx += NTHR) {
        int col = idx & 3, i = idx >> 2;
        s.wca[col][i] = __ldg(&W_ca[(size_t)i * HS + c4 + col]);
        s.wcm[col][i] = __ldg(&W_cm[(size_t)i * HS + c4 + col]);
    }
    if (cta < MBK) {
        for (int i = tid; i < 1536; i += NTHR) s.wrp[i] = __ldg(&W_rp[(size_t)i * MBK + cta]);
        for (int i = tid; i < 512; i += NTHR) {
            s.wwpa[i] = __ldg(&W_wpa[(size_t)i * MBK + cta]);
            s.wwpm[i] = __ldg(&W_wpm[(size_t)i * MBK + cta]);
        }
        if (tid == 0) s.brp1 = b_rp[cta];
    } else if (cta < MBK + 3) {
        for (int i = tid; i < 1536; i += NTHR) s.wrp[i] = __ldg(&W_wp[(size_t)i * 3 + (cta - MBK)]);
        if (tid == 0) s.bwp1 = b_wp[cta - MBK];
    }
    if (tid < 4) s.brh[tid] = b_rh[c4 + tid];
    for (int idx = tid; idx < 4 * MBK; idx += NTHR) (&s.mem[0][0])[idx] = 0.f;
    __syncthreads();

    unsigned int barc = 0;

    for (int t = 0; t < T_STEPS; ++t) {
        // ================= phase 1: state load + content cols + logits =================
        if (t == 0) {
            for (int i = tid; i < 1536; i += NTHR) s.sx[i] = 0.f;
        } else {
            for (int i = tid; i < 1536; i += NTHR) s.sx[i] = __ldcg(&g_state[i]);
        }
        if (tid < 4) {
            s.pre_ca [tid] = g_pre_ca [(size_t)t * HS + c4 + tid];
            s.pre_cm [tid] = g_pre_cm [(size_t)t * HS + c4 + tid];
            s.pre_rha[tid] = g_pre_rha[(size_t)t * HS + c4 + tid];
            s.pre_rhm[tid] = g_pre_rhm[(size_t)t * HS + c4 + tid];
        }
        if (tid == 4 && cta < MBK) {
            s.pre_wpa1 = g_pre_wpa[(size_t)t * MBK + cta];
            s.pre_wpm1 = g_pre_wpm[(size_t)t * MBK + cta];
        }
        __syncthreads();

        // Pass A: c_a (warps 0-3) / c_m (warps 4-7)
        {
            int col = warp & 3;
            const float* w = (warp < 4) ? s.wca[col] : s.wcm[col];
            const float* x = (warp < 4) ? s.sx : (s.sx + 512);
            float acc = 0.f;
#pragma unroll
            for (int i = 0; i < 512; i += 32) acc = fmaf(x[i + lane], w[i + lane], acc);
            acc = warpsum(acc);
            if (lane == 0) {
                if (warp < 4) s.ca_own[col] = fmaxf(acc + s.pre_ca[col], 0.f);
                else          s.cm_own[col] = fmaxf(acc + s.pre_cm[col], 0.f);
            }
        }
        // Pass B: ar/aw logit (warps 0-5), aw_a/aw_m logits (warps 6-7)
        if (cta < MBK + 3) {
            if (warp < 6) {
                float acc = 0.f; int base = warp * 256;
#pragma unroll
                for (int i = 0; i < 256; i += 32)
                    acc = fmaf(s.sx[base + i + lane], s.wrp[base + i + lane], acc);
                acc = warpsum(acc);
                if (lane == 0) s.red[warp] = acc;
            } else if (cta < MBK) {
                const float* w = (warp == 6) ? s.wwpa : s.wwpm;
                const float* x = (warp == 6) ? s.sx : (s.sx + 512);
                float acc = 0.f;
#pragma unroll
                for (int i = 0; i < 512; i += 32) acc = fmaf(x[i + lane], w[i + lane], acc);
                acc = warpsum(acc);
                if (lane == 0) s.red[warp] = acc;
            }
        }
        __syncthreads();
        if (tid == 0 && cta < MBK + 3) {
            float v = s.red[0] + s.red[1] + s.red[2] + s.red[3] + s.red[4] + s.red[5];
            if (cta < MBK) __stcg(&g_arlog[cta], v + s.brp1);
            else           __stcg(&g_awlog[cta - MBK], v + s.bwp1);
        }
        if (tid == 32 && cta < MBK) {
            __stcg(&g_awalog[cta], s.red[6] + s.pre_wpa1);
            __stcg(&g_awmlog[cta], s.red[7] + s.pre_wpm1);
        }
        ++barc; gbar_arrive(cta, barc); gbar_wait(barc);

        // ================= phase 2: softmaxes + r =================
        if (tid < MBK) {
            s.lar [tid] = __ldcg(&g_arlog [tid]);
            s.lawa[tid] = __ldcg(&g_awalog[tid]);
            s.lawm[tid] = __ldcg(&g_awmlog[tid]);
        } else if (tid < MBK + 3) {
            s.law[tid - MBK] = __ldcg(&g_awlog[tid - MBK]);
        }
        __syncthreads();

        if (warp < 3) {
            const float* L = (warp == 0) ? s.lar : (warp == 1) ? s.lawa : s.lawm;
            float* P       = (warp == 0) ? s.par : (warp == 1) ? s.pawa : s.pawm;
            float v[4];
#pragma unroll
            for (int k = 0; k < 4; k++) { int j = lane + 32 * k; v[k] = (j < MBK) ? L[j] : -1e30f; }
            float m = fmaxf(fmaxf(v[0], v[1]), fmaxf(v[2], v[3]));
#pragma unroll
            for (int o = 16; o; o >>= 1) m = fmaxf(m, __shfl_xor_sync(0xFFFFFFFFu, m, o));
            float e[4], sum = 0.f;
#pragma unroll
            for (int k = 0; k < 4; k++) {
                int j = lane + 32 * k;
                e[k] = (j < MBK) ? expf(v[k] - m) : 0.f;
                sum += e[k];
            }
            sum = warpsum(sum);
            float inv = 1.f / sum;
#pragma unroll
            for (int k = 0; k < 4; k++) { int j = lane + 32 * k; if (j < MBK) P[j] = e[k] * inv; }
        } else if (warp == 3 && lane == 0) {
            float l0 = s.law[0], l1 = s.law[1], l2 = s.law[2];
            float m = fmaxf(l0, fmaxf(l1, l2));
            float e0 = expf(l0 - m), e1 = expf(l1 - m), e2 = expf(l2 - m);
            float inv = 1.f / (e0 + e1 + e2);
            s.aw[0] = e0 * inv; s.aw[1] = e1 * inv; s.aw[2] = e2 * inv;
        }
        __syncthreads();

        // r[owned cols] from OLD mem
        if (warp < 4) {
            int col = warp; float acc = 0.f;
            for (int j = lane; j < MBK; j += 32) acc = fmaf(s.par[j], s.mem[col][j], acc);
            acc = warpsum(acc);
            if (lane == 0) __stcg(&g_r[c4 + col], acc);
        }
        ++barc; gbar_arrive(cta, barc);

        // mem update (purely local) overlaps the barrier wait
        {
            float aw0 = s.aw[0], aw1 = s.aw[1], aw2 = s.aw[2];
            for (int idx = tid; idx < 4 * MBK; idx += NTHR) {
                int col = idx & 3, j = idx >> 2;
                s.mem[col][j] = aw0 * s.mem[col][j]
                              + aw1 * s.pawa[j] * s.ca_own[col]
                              + aw2 * s.pawm[j] * s.cm_own[col];
            }
        }
        gbar_wait(barc);

        // ================= phase 3: h1 / ha1 / hm1 =================
        for (int i = tid; i < 512; i += NTHR) s.r[i] = __ldcg(&g_r[i]);
        __syncthreads();
#pragma unroll
        for (int rep = 0; rep < 2; rep++) {
            int task = warp + rep * 8;
            if (task < 12) {
                int mat = task >> 2, col = task & 3;
                const float* w = (mat == 0) ? s.wrh[col] : (mat == 1) ? s.wrha[col] : s.wrhm[col];
                const float* x = (mat == 0) ? (s.sx + 1024) : (mat == 1) ? s.sx : (s.sx + 512);
                float acc = 0.f;
#pragma unroll
                for (int i = lane; i < 512; i += 32)
                    acc = fmaf(s.r[i], w[i], fmaf(x[i], w[512 + i], acc));
                acc = warpsum(acc);
                if (lane == 0) {
                    if (mat == 0) {
                        float h1 = fmaxf(acc + s.brh[col], 0.f);
                        __stcg(&g_state[1024 + c4 + col], h1);
                        out[(size_t)t * HS + c4 + col] = h1;
                    } else if (mat == 1) {
                        __stcg(&g_state[c4 + col], fmaxf(acc + s.pre_rha[col], 0.f));
                    } else {
                        __stcg(&g_state[512 + c4 + col], fmaxf(acc + s.pre_rhm[col], 0.f));
                    }
                }
            }
        }
        ++barc; gbar_arrive(cta, barc); gbar_wait(barc);
    }
}

// =====================================================================
extern "C" void kernel_launch(void* const* d_in, const int* in_sizes, int n_in,
                              void* d_out, int out_size)
{
    const float* Xa    = (const float*)d_in[0];
    const float* Xm    = (const float*)d_in[1];
    const float* W_ca  = (const float*)d_in[2];
    const float* b_ca  = (const float*)d_in[3];
    const float* W_cm  = (const float*)d_in[4];
    const float* b_cm  = (const float*)d_in[5];
    const float* W_wp  = (const float*)d_in[6];
    const float* b_wp  = (const float*)d_in[7];
    const float* W_wpa = (const float*)d_in[8];
    const float* b_wpa = (const float*)d_in[9];
    const float* W_wpm = (const float*)d_in[10];
    const float* b_wpm = (const float*)d_in[11];
    const float* W_rp  = (const float*)d_in[12];
    const float* b_rp  = (const float*)d_in[13];
    const float* W_rh  = (const float*)d_in[14];
    const float* b_rh  = (const float*)d_in[15];
    const float* W_rha = (const float*)d_in[16];
    const float* W_rhm = (const float*)d_in[18];
    float* out = (float*)d_out;

    static bool attr_set = false;
    if (!attr_set) {
        cudaFuncSetAttribute(seq_kernel, cudaFuncAttributeMaxDynamicSharedMemorySize,
                             (int)sizeof(SeqSmem));
        attr_set = true;
    }

    dim3 ggrid(4, T_STEPS / 128, 6);
    gemm6_kernel<<<ggrid, 256>>>(Xa, Xm,
                                 W_rha, (const float*)d_in[17],
                                 W_rhm, (const float*)d_in[19],
                                 W_ca, b_ca, W_cm, b_cm,
                                 W_wpa, b_wpa, W_wpm, b_wpm);
    reset_kernel<<<1, 512>>>();
    seq_kernel<<<NCTA, NTHR, sizeof(SeqSmem)>>>(W_ca, W_cm, W_wp, b_wp, W_wpa, W_wpm,
                                                W_rp, b_rp, W_rh, b_rh, W_rha, W_rhm,
                                                out);
}

// round 9
// speedup vs baseline: 1.9547x; 1.4715x over previous
#include <cuda_runtime.h>
#include <cuda_bf16.h>
#include <math.h>
#include <stdint.h>

#define T_STEPS 4096
#define HS 512
#define INSZ 2048
#define MBK 100
#define NCTA 128
#define NTHR 512

// ---------------- device scratch (allocations are forbidden) ----------------
__device__ float g_pre_rha[T_STEPS * HS];
__device__ float g_pre_rhm[T_STEPS * HS];
__device__ float g_pre_ca [T_STEPS * HS];
__device__ float g_pre_cm [T_STEPS * HS];
__device__ float g_pre_wpa[T_STEPS * MBK];
__device__ float g_pre_wpm[T_STEPS * MBK];
__device__ float g_state[3 * HS];          // [ha(512) | hm(512) | h(512)]
__device__ float g_r[HS];
// logit accumulators, double buffered: [0..99]=ar, [100..102]=aw,
// [103..202]=aw_a(ha part), [203..302]=aw_m(hm part)
__device__ float g_acc[2][320];
__device__ unsigned int g_bar;

__device__ __forceinline__ float warpsum(float v) {
#pragma unroll
    for (int o = 16; o; o >>= 1) v += __shfl_xor_sync(0xFFFFFFFFu, v, o);
    return v;
}

// ---------------- single-counter grid barrier (R6-proven), split arrive/wait
__device__ __forceinline__ void gbar_arrive() {
    __syncthreads();
    if (threadIdx.x == 0) {
        __threadfence();
        atomicAdd(&g_bar, 1u);
    }
}
__device__ __forceinline__ void gbar_wait(unsigned int target) {
    if (threadIdx.x == 0) {
        int spins = 0;
        while (*(volatile unsigned int*)&g_bar < target) {
            if (++spins > 8) __nanosleep(40);
        }
        __threadfence();
    }
    __syncthreads();
}

__global__ void reset_kernel() {
    int i = threadIdx.x;
    if (i == 0) g_bar = 0u;
    float* a = &g_acc[0][0];
    for (int j = i; j < 2 * 320; j += blockDim.x) a[j] = 0.f;
}

// =====================================================================
// Precompute GEMMs (unchanged from R6): C[4096,N] = X @ W[rowOff:+2048, :N] + bias
// =====================================================================
__global__ __launch_bounds__(256)
void gemm6_kernel(const float* __restrict__ Xa, const float* __restrict__ Xm,
                  const float* __restrict__ W_rha, const float* __restrict__ b_rha,
                  const float* __restrict__ W_rhm, const float* __restrict__ b_rhm,
                  const float* __restrict__ W_ca,  const float* __restrict__ b_ca,
                  const float* __restrict__ W_cm,  const float* __restrict__ b_cm,
                  const float* __restrict__ W_wpa, const float* __restrict__ b_wpa,
                  const float* __restrict__ W_wpm, const float* __restrict__ b_wpm)
{
    const float* A; const float* B; const float* bias; float* C; int N; int rowOff;
    switch (blockIdx.z) {
        case 0: A = Xa; B = W_rha; bias = b_rha; C = g_pre_rha; N = HS;  rowOff = 0;   break;
        case 1: A = Xm; B = W_rhm; bias = b_rhm; C = g_pre_rhm; N = HS;  rowOff = 0;   break;
        case 2: A = Xa; B = W_ca;  bias = b_ca;  C = g_pre_ca;  N = HS;  rowOff = HS;  break;
        case 3: A = Xm; B = W_cm;  bias = b_cm;  C = g_pre_cm;  N = HS;  rowOff = HS;  break;
        case 4: A = Xa; B = W_wpa; bias = b_wpa; C = g_pre_wpa; N = MBK; rowOff = HS;  break;
        default:A = Xm; B = W_wpm; bias = b_wpm; C = g_pre_wpm; N = MBK; rowOff = HS;  break;
    }
    if ((int)blockIdx.x * 128 >= N) return;

    const int K = INSZ;
    __shared__ float As[8][128];
    __shared__ float Bs[8][128];
    const int tid  = threadIdx.x;
    const int tx   = tid & 15, ty = tid >> 4;
    const int brow = blockIdx.y, bcol = blockIdx.x;

    const int arow = tid >> 1, akq = (tid & 1) * 4;
    const float* Ag = A + (size_t)(brow * 128 + arow) * K + akq;
    const int bk = tid >> 5, bc = (tid & 31) * 4;
    const int gcol = bcol * 128 + bc;
    const bool bok = (gcol + 3 < N);

    float acc[8][8];
#pragma unroll
    for (int i = 0; i < 8; i++)
#pragma unroll
        for (int j = 0; j < 8; j++) acc[i][j] = 0.f;

    for (int k0 = 0; k0 < K; k0 += 8) {
        float4 av = *(const float4*)(Ag + k0);
        As[akq + 0][arow] = av.x; As[akq + 1][arow] = av.y;
        As[akq + 2][arow] = av.z; As[akq + 3][arow] = av.w;
        float4 bv = bok ? *(const float4*)(B + (size_t)(rowOff + k0 + bk) * N + gcol)
                        : make_float4(0.f, 0.f, 0.f, 0.f);
        *(float4*)&Bs[bk][bc] = bv;
        __syncthreads();
#pragma unroll
        for (int kk = 0; kk < 8; ++kk) {
            float ra[8], rb[8];
            *(float4*)(ra)     = *(const float4*)&As[kk][ty * 4];
            *(float4*)(ra + 4) = *(const float4*)&As[kk][64 + ty * 4];
            *(float4*)(rb)     = *(const float4*)&Bs[kk][tx * 4];
            *(float4*)(rb + 4) = *(const float4*)&Bs[kk][64 + tx * 4];
#pragma unroll
            for (int i = 0; i < 8; i++)
#pragma unroll
                for (int j = 0; j < 8; j++) acc[i][j] = fmaf(ra[i], rb[j], acc[i][j]);
        }
        __syncthreads();
    }
#pragma unroll
    for (int i = 0; i < 8; i++) {
        int row = brow * 128 + ((i < 4) ? (ty * 4 + i) : (64 + ty * 4 + i - 4));
#pragma unroll
        for (int j = 0; j < 8; j++) {
            int col = bcol * 128 + ((j < 4) ? (tx * 4 + j) : (64 + tx * 4 + j - 4));
            if (col < N) C[(size_t)row * N + col] = acc[i][j] + bias[col];
        }
    }
}

// =====================================================================
// Persistent sequential kernel: 128 CTAs x 512 threads, each owns 4 HS columns.
// 2 grid barriers per step (logits are PUSHED forward from phase B).
// =====================================================================
struct SeqSmem {
    float wrh [4][1024];   // W_rh  col slices: rows [r(512) | h(512)]
    float wrha[4][1024];   // W_rha rows 2048..3071: [r | ha]
    float wrhm[4][1024];   // W_rhm rows 2048..3071: [r | hm]
    float wca [4][512];    // W_ca rows 0..511 (ha)
    float wcm [4][512];    // W_cm rows 0..511 (hm)
    float wrp_r [12][104]; // W_rp rows owned (ha0-3,hm0-3,h0-3) x 100 logits
    float wwp_r [12][4];   // W_wp rows owned x 3
    float wwpa_r[4][104];  // W_wpa rows c4..c4+3 (ha part) x 100
    float wwpm_r[4][104];
    float mem [4][MBK];    // mem[:, owned cols], col-major
    float sx  [1536];      // state entering the step: [ha | hm | h]
    float r   [512];
    float lar [MBK], lawa[MBK], lawm[MBK], law[3];
    float par [MBK], pawa[MBK], pawm[MBK], aw[3];
    float snew[12];        // new state own comps: [ha1(4) | hm1(4) | h1(4)]
    float pre_ca[4], pre_cm[4], pre_rha[4], pre_rhm[4];
    float ca_own[4], cm_own[4];
    float brh[4];
    float brp_s[MBK], bwp_s[3];
};

__global__ __launch_bounds__(NTHR, 1)
void seq_kernel(const float* __restrict__ W_ca,  const float* __restrict__ W_cm,
                const float* __restrict__ W_wp,  const float* __restrict__ b_wp,
                const float* __restrict__ W_wpa, const float* __restrict__ W_wpm,
                const float* __restrict__ W_rp,  const float* __restrict__ b_rp,
                const float* __restrict__ W_rh,  const float* __restrict__ b_rh,
                const float* __restrict__ W_rha, const float* __restrict__ W_rhm,
                float* __restrict__ out)
{
    extern __shared__ float smem_raw[];
    SeqSmem& s = *reinterpret_cast<SeqSmem*>(smem_raw);
    const int tid  = threadIdx.x;
    const int warp = tid >> 5, lane = tid & 31;
    const int cta  = blockIdx.x;
    const int c4   = cta * 4;

    // ---- one-time weight load ----
    for (int idx = tid; idx < 4 * 1024; idx += NTHR) {
        int col = idx & 3, i = idx >> 2;
        s.wrh [col][i] = __ldg(&W_rh [(size_t)i * HS + c4 + col]);
        s.wrha[col][i] = __ldg(&W_rha[(size_t)(INSZ + i) * HS + c4 + col]);
        s.wrhm[col][i] = __ldg(&W_rhm[(size_t)(INSZ + i) * HS + c4 + col]);
    }
    for (int idx = tid; idx < 4 * 512; idx += NTHR) {
        int col = idx & 3, i = idx >> 2;
        s.wca[col][i] = __ldg(&W_ca[(size_t)i * HS + c4 + col]);
        s.wcm[col][i] = __ldg(&W_cm[(size_t)i * HS + c4 + col]);
    }
    // push-weight rows (owned state dims -> all logits)
    for (int idx = tid; idx < 12 * MBK; idx += NTHR) {
        int k = idx / MBK, j = idx % MBK;
        int row = (k < 4) ? (c4 + k) : (k < 8) ? (512 + c4 + k - 4) : (1024 + c4 + k - 8);
        s.wrp_r[k][j] = __ldg(&W_rp[(size_t)row * MBK + j]);
    }
    if (tid < 36) {
        int k = tid / 3, j = tid % 3;
        int row = (k < 4) ? (c4 + k) : (k < 8) ? (512 + c4 + k - 4) : (1024 + c4 + k - 8);
        s.wwp_r[k][j] = __ldg(&W_wp[(size_t)row * 3 + j]);
    }
    for (int idx = tid; idx < 4 * MBK; idx += NTHR) {
        int k = idx / MBK, j = idx % MBK;
        s.wwpa_r[k][j] = __ldg(&W_wpa[(size_t)(c4 + k) * MBK + j]);
        s.wwpm_r[k][j] = __ldg(&W_wpm[(size_t)(c4 + k) * MBK + j]);
    }
    for (int i = tid; i < MBK; i += NTHR) s.brp_s[i] = __ldg(&b_rp[i]);
    if (tid < 3) s.bwp_s[tid] = b_wp[tid];
    if (tid < 4) s.brh[tid] = b_rh[c4 + tid];
    for (int idx = tid; idx < 4 * MBK; idx += NTHR) (&s.mem[0][0])[idx] = 0.f;
    __syncthreads();

    unsigned int barc = 0;

    for (int t = 0; t < T_STEPS; ++t) {
        const int buf  = t & 1;
        const int nbuf = buf ^ 1;

        // ============ phase A: read state+logits, softmax, c dots, r + mem ============
        if (t == 0) {
            for (int i = tid; i < 1536; i += NTHR) s.sx[i] = 0.f;
        } else {
            for (int i = tid; i < 1536; i += NTHR) s.sx[i] = __ldcg(&g_state[i]);
        }
        if (tid < MBK) {
            s.lar [tid] = __ldcg(&g_acc[buf][tid])       + s.brp_s[tid];
            s.lawa[tid] = __ldcg(&g_acc[buf][103 + tid]) + __ldcg(&g_pre_wpa[(size_t)t * MBK + tid]);
            s.lawm[tid] = __ldcg(&g_acc[buf][203 + tid]) + __ldcg(&g_pre_wpm[(size_t)t * MBK + tid]);
        } else if (tid < MBK + 3) {
            s.law[tid - MBK] = __ldcg(&g_acc[buf][tid]) + s.bwp_s[tid - MBK];
        }
        if (tid < 4) {
            s.pre_ca [tid] = __ldcg(&g_pre_ca [(size_t)t * HS + c4 + tid]);
            s.pre_cm [tid] = __ldcg(&g_pre_cm [(size_t)t * HS + c4 + tid]);
            s.pre_rha[tid] = __ldcg(&g_pre_rha[(size_t)t * HS + c4 + tid]);
            s.pre_rhm[tid] = __ldcg(&g_pre_rhm[(size_t)t * HS + c4 + tid]);
        }
        __syncthreads();

        // warps 0-7: c_a / c_m column dots;  warps 8-10: 100-wide softmaxes; warp 11: aw
        if (warp < 8) {
            int col = warp & 3;
            const float* w = (warp < 4) ? s.wca[col] : s.wcm[col];
            const float* x = (warp < 4) ? s.sx : (s.sx + 512);
            float acc = 0.f;
#pragma unroll
            for (int i = 0; i < 512; i += 32) acc = fmaf(x[i + lane], w[i + lane], acc);
            acc = warpsum(acc);
            if (lane == 0) {
                if (warp < 4) s.ca_own[col] = fmaxf(acc + s.pre_ca[col], 0.f);
                else          s.cm_own[col] = fmaxf(acc + s.pre_cm[col], 0.f);
            }
        } else if (warp < 11) {
            const float* L = (warp == 8) ? s.lar : (warp == 9) ? s.lawa : s.lawm;
            float* P       = (warp == 8) ? s.par : (warp == 9) ? s.pawa : s.pawm;
            float v[4];
#pragma unroll
            for (int k = 0; k < 4; k++) { int j = lane + 32 * k; v[k] = (j < MBK) ? L[j] : -1e30f; }
            float m = fmaxf(fmaxf(v[0], v[1]), fmaxf(v[2], v[3]));
#pragma unroll
            for (int o = 16; o; o >>= 1) m = fmaxf(m, __shfl_xor_sync(0xFFFFFFFFu, m, o));
            float e[4], sum = 0.f;
#pragma unroll
            for (int k = 0; k < 4; k++) {
                int j = lane + 32 * k;
                e[k] = (j < MBK) ? expf(v[k] - m) : 0.f;
                sum += e[k];
            }
            sum = warpsum(sum);
            float inv = 1.f / sum;
#pragma unroll
            for (int k = 0; k < 4; k++) { int j = lane + 32 * k; if (j < MBK) P[j] = e[k] * inv; }
        } else if (warp == 11 && lane == 0) {
            float l0 = s.law[0], l1 = s.law[1], l2 = s.law[2];
            float m = fmaxf(l0, fmaxf(l1, l2));
            float e0 = expf(l0 - m), e1 = expf(l1 - m), e2 = expf(l2 - m);
            float inv = 1.f / (e0 + e1 + e2);
            s.aw[0] = e0 * inv; s.aw[1] = e1 * inv; s.aw[2] = e2 * inv;
        }
        __syncthreads();

        // warps 0-3: fused r-dot over OLD mem + in-place mem update (one pass)
        if (warp < 4) {
            int col = warp;
            float aw0 = s.aw[0], aw1c = s.aw[1] * s.ca_own[col], aw2c = s.aw[2] * s.cm_own[col];
            float acc = 0.f;
#pragma unroll
            for (int k = 0; k < 4; k++) {
                int j = lane + 32 * k;
                if (j < MBK) {
                    float old = s.mem[col][j];
                    acc = fmaf(s.par[j], old, acc);
                    s.mem[col][j] = fmaf(aw0, old, fmaf(aw1c, s.pawa[j], aw2c * s.pawm[j]));
                }
            }
            acc = warpsum(acc);
            if (lane == 0) __stcg(&g_r[c4 + col], acc);
        }
        ++barc; gbar_arrive(); gbar_wait(barc * NCTA);

        // ============ phase B: h1/ha1/hm1 dots + push next-step logits ============
        for (int i = tid; i < 512; i += NTHR) s.r[i] = __ldcg(&g_r[i]);
        // zero the just-consumed accumulator buffer (disjoint slices)
        if (warp == 12 && lane < 4 && cta < 80) __stcg(&g_acc[buf][c4 + lane], 0.f);
        __syncthreads();

        if (warp < 12) {
            int mat = warp >> 2, col = warp & 3;
            const float* w = (mat == 0) ? s.wrh[col] : (mat == 1) ? s.wrha[col] : s.wrhm[col];
            const float* x = (mat == 0) ? (s.sx + 1024) : (mat == 1) ? s.sx : (s.sx + 512);
            float acc = 0.f;
#pragma unroll
            for (int i = lane; i < 512; i += 32)
                acc = fmaf(s.r[i], w[i], fmaf(x[i], w[512 + i], acc));
            acc = warpsum(acc);
            if (lane == 0) {
                if (mat == 0) {
                    float h1 = fmaxf(acc + s.brh[col], 0.f);
                    s.snew[8 + col] = h1;
                    __stcg(&g_state[1024 + c4 + col], h1);
                    out[(size_t)t * HS + c4 + col] = h1;
                } else if (mat == 1) {
                    float ha1 = fmaxf(acc + s.pre_rha[col], 0.f);
                    s.snew[col] = ha1;
                    __stcg(&g_state[c4 + col], ha1);
                } else {
                    float hm1 = fmaxf(acc + s.pre_rhm[col], 0.f);
                    s.snew[4 + col] = hm1;
                    __stcg(&g_state[512 + c4 + col], hm1);
                }
            }
        }
        __syncthreads();

        // push partial logits for step t+1 (303 spread-address float REDs)
        if (t + 1 < T_STEPS && tid < 303) {
            float p = 0.f;
            int slot;
            if (tid < MBK) {                       // ar logit
#pragma unroll
                for (int k = 0; k < 12; k++) p = fmaf(s.snew[k], s.wrp_r[k][tid], p);
                slot = tid;
            } else if (tid < MBK + 3) {            // aw logit
                int j = tid - MBK;
#pragma unroll
                for (int k = 0; k < 12; k++) p = fmaf(s.snew[k], s.wwp_r[k][j], p);
                slot = 100 + j;
            } else if (tid < 203) {                // aw_a (ha part)
                int j = tid - 103;
#pragma unroll
                for (int k = 0; k < 4; k++) p = fmaf(s.snew[k], s.wwpa_r[k][j], p);
                slot = 103 + j;
            } else {                               // aw_m (hm part)
                int j = tid - 203;
#pragma unroll
                for (int k = 0; k < 4; k++) p = fmaf(s.snew[4 + k], s.wwpm_r[k][j], p);
                slot = 203 + j;
            }
            atomicAdd(&g_acc[nbuf][slot], p);
        }
        ++barc; gbar_arrive(); gbar_wait(barc * NCTA);
    }
}

// =====================================================================
extern "C" void kernel_launch(void* const* d_in, const int* in_sizes, int n_in,
                              void* d_out, int out_size)
{
    const float* Xa    = (const float*)d_in[0];
    const float* Xm    = (const float*)d_in[1];
    const float* W_ca  = (const float*)d_in[2];
    const float* b_ca  = (const float*)d_in[3];
    const float* W_cm  = (const float*)d_in[4];
    const float* b_cm  = (const float*)d_in[5];
    const float* W_wp  = (const float*)d_in[6];
    const float* b_wp  = (const float*)d_in[7];
    const float* W_wpa = (const float*)d_in[8];
    const float* b_wpa = (const float*)d_in[9];
    const float* W_wpm = (const float*)d_in[10];
    const float* b_wpm = (const float*)d_in[11];
    const float* W_rp  = (const float*)d_in[12];
    const float* b_rp  = (const float*)d_in[13];
    const float* W_rh  = (const float*)d_in[14];
    const float* b_rh  = (const float*)d_in[15];
    const float* W_rha = (const float*)d_in[16];
    const float* W_rhm = (const float*)d_in[18];
    float* out = (float*)d_out;

    static bool attr_set = false;
    if (!attr_set) {
        cudaFuncSetAttribute(seq_kernel, cudaFuncAttributeMaxDynamicSharedMemorySize,
                             (int)sizeof(SeqSmem));
        attr_set = true;
    }

    dim3 ggrid(4, T_STEPS / 128, 6);
    gemm6_kernel<<<ggrid, 256>>>(Xa, Xm,
                                 W_rha, (const float*)d_in[17],
                                 W_rhm, (const float*)d_in[19],
                                 W_ca, b_ca, W_cm, b_cm,
                                 W_wpa, b_wpa, W_wpm, b_wpm);
    reset_kernel<<<1, 512>>>();
    seq_kernel<<<NCTA, NTHR, sizeof(SeqSmem)>>>(W_ca, W_cm, W_wp, b_wp, W_wpa, W_wpm,
                                                W_rp, b_rp, W_rh, b_rh, W_rha, W_rhm,
                                                out);
}